// round 1
// baseline (speedup 1.0000x reference)
#include <cuda_runtime.h>
#include <math.h>

// ---------------- problem constants ----------------
#define BB   8
#define NN   1024
#define IND  64
#define HIDD 96
#define MAXH 3
#define NEG  0.2f

// ---------------- scratch (device globals, no allocation) ----------------
__device__ float    g_x[6][BB * NN * HIDD];        // x0..x5
__device__ float    g_h [BB * NN * HIDD];          // current layer h = in @ W
__device__ float    g_es[BB * MAXH * NN];
__device__ float    g_ed[BB * MAXH * NN];
__device__ float    g_A1[BB * MAXH * NN];
__device__ float    g_A2[BB * MAXH * NN];
__device__ float    g_E1[BB * MAXH * NN];
__device__ float    g_E2[BB * MAXH * NN];
__device__ unsigned g_adjb[NN * NN / 32];          // adjacency bitmask
__device__ float    g_gates[BB * 2];
__device__ float    g_pool[5 * 8 * BB * HIDD];     // [slot][chunk][b][col] partial sums

// ---------------- helpers ----------------
__device__ __forceinline__ float warpSum(float v) {
    #pragma unroll
    for (int o = 16; o; o >>= 1) v += __shfl_xor_sync(0xffffffffu, v, o);
    return v;
}
__device__ __forceinline__ float warpMax(float v) {
    #pragma unroll
    for (int o = 16; o; o >>= 1) v = fmaxf(v, __shfl_xor_sync(0xffffffffu, v, o));
    return v;
}
__device__ __forceinline__ float eluf(float x) { return x > 0.f ? x : expm1f(x); }

__device__ __forceinline__ float* bufsel(int id) { return g_x[id]; }

// ---------------- 1. adjacency -> bitmask ----------------
__global__ void k_adjbits(const int* __restrict__ adj) {
    int gw   = (blockIdx.x * blockDim.x + threadIdx.x) >> 5;   // word index [0, 32768)
    int lane = threadIdx.x & 31;
    unsigned m = __ballot_sync(0xffffffffu, adj[gw * 32 + lane] > 0);
    if (lane == 0) g_adjb[gw] = m;
}

// ---------------- 2. LayerNorm + pre Linear + ELU -> x0 ----------------
__global__ __launch_bounds__(256) void k_ln_pre(
    const float* __restrict__ x, const float* __restrict__ ln_g,
    const float* __restrict__ ln_b, const float* __restrict__ W,
    const float* __restrict__ bias)
{
    __shared__ float Ws[IND * HIDD];
    __shared__ float xs[8][IND];
    int tid = threadIdx.x, warp = tid >> 5, lane = tid & 31;
    for (int i = tid; i < IND * HIDD; i += 256) Ws[i] = W[i];

    int row = blockIdx.x * 8 + warp;                 // [0, B*N)
    const float* xr = x + row * IND;
    float v0 = xr[lane], v1 = xr[lane + 32];
    float mu = warpSum(v0 + v1) * (1.f / IND);
    float d0 = v0 - mu, d1 = v1 - mu;
    float var = warpSum(d0 * d0 + d1 * d1) * (1.f / IND);
    float rs = rsqrtf(var + 1e-5f);
    xs[warp][lane]      = d0 * rs * ln_g[lane]      + ln_b[lane];
    xs[warp][lane + 32] = d1 * rs * ln_g[lane + 32] + ln_b[lane + 32];
    __syncthreads();

    float a0 = bias[lane], a1 = bias[lane + 32], a2 = bias[lane + 64];
    #pragma unroll
    for (int d = 0; d < IND; d++) {
        float xv = xs[warp][d];
        a0 += xv * Ws[d * HIDD + lane];
        a1 += xv * Ws[d * HIDD + lane + 32];
        a2 += xv * Ws[d * HIDD + lane + 64];
    }
    float* o = g_x[0] + row * HIDD;
    o[lane] = eluf(a0); o[lane + 32] = eluf(a1); o[lane + 64] = eluf(a2);
}

// ---------------- 3. h = mix(x) @ W, plus es/ed per head ----------------
// mode 0: in = xa
// mode 1: in = (1-g)*xa + g*xb,  g = gates[b*2 + gidx]
// mode 2: in = xa + 0.5*(wt*xb + wr*xc)
__global__ __launch_bounds__(256) void k_gemm_h(
    int ia, int ib, int ic, int mode, int gidx,
    const float* __restrict__ W, const float* __restrict__ a_src,
    const float* __restrict__ a_dst, int H)
{
    __shared__ float Ws[HIDD * HIDD];
    __shared__ float ins[8][HIDD];
    int tid = threadIdx.x, warp = tid >> 5, lane = tid & 31;
    for (int i = tid; i < HIDD * HIDD; i += 256) Ws[i] = W[i];

    int row = blockIdx.x * 8 + warp;
    int b = row >> 10;

    float c_a = 1.f, c_b = 0.f, c_c = 0.f;
    if (mode == 1) { float g = g_gates[b * 2 + gidx]; c_a = 1.f - g; c_b = g; }
    else if (mode == 2) {
        float wt = g_gates[b * 2], wr = g_gates[b * 2 + 1];
        c_b = 0.5f * wt; c_c = 0.5f * wr;
    }
    const float* A = bufsel(ia) + row * HIDD;
    const float* Bp = bufsel(ib) + row * HIDD;
    const float* Cp = bufsel(ic) + row * HIDD;
    #pragma unroll
    for (int k = 0; k < 3; k++) {
        int c = lane + 32 * k;
        float v = c_a * A[c];
        if (mode >= 1) v += c_b * Bp[c];
        if (mode == 2) v += c_c * Cp[c];
        ins[warp][c] = v;
    }
    __syncthreads();

    float a0 = 0.f, a1 = 0.f, a2 = 0.f;
    #pragma unroll
    for (int d = 0; d < HIDD; d++) {
        float xv = ins[warp][d];
        a0 += xv * Ws[d * HIDD + lane];
        a1 += xv * Ws[d * HIDD + lane + 32];
        a2 += xv * Ws[d * HIDD + lane + 64];
    }
    float* hp = g_h + row * HIDD;
    hp[lane] = a0; hp[lane + 32] = a1; hp[lane + 64] = a2;

    int n = row & (NN - 1);
    if (H == 1) {
        float ps = a0 * a_src[lane] + a1 * a_src[lane + 32] + a2 * a_src[lane + 64];
        float pd = a0 * a_dst[lane] + a1 * a_dst[lane + 32] + a2 * a_dst[lane + 64];
        ps = warpSum(ps); pd = warpSum(pd);
        if (lane == 0) { g_es[b * NN + n] = ps; g_ed[b * NN + n] = pd; }
    } else {  // H == 3, D = 32: head h lives in columns [h*32, h*32+32)
        float s0 = warpSum(a0 * a_src[lane]);
        float s1 = warpSum(a1 * a_src[32 + lane]);
        float s2 = warpSum(a2 * a_src[64 + lane]);
        float e0 = warpSum(a0 * a_dst[lane]);
        float e1 = warpSum(a1 * a_dst[32 + lane]);
        float e2 = warpSum(a2 * a_dst[64 + lane]);
        if (lane == 0) {
            g_es[(b * 3 + 0) * NN + n] = s0; g_ed[(b * 3 + 0) * NN + n] = e0;
            g_es[(b * 3 + 1) * NN + n] = s1; g_ed[(b * 3 + 1) * NN + n] = e1;
            g_es[(b * 3 + 2) * NN + n] = s2; g_ed[(b * 3 + 2) * NN + n] = e2;
        }
    }
}

// ---------------- 4. per-row masked max + exp factor precompute ----------------
// w_ij = exp(lrelu(es_i+ed_j) - m_i) factorizes (lrelu piecewise linear):
//   t>0: A1_i*E1_j with A1 = exp(es-m+maxed),       E1 = exp(ed-maxed)
//   t<=0: A2_i*E2_j with A2 = exp(0.2*(es+maxed)-m), E2 = exp(0.2*(ed-maxed))
__global__ __launch_bounds__(256) void k_prep() {
    __shared__ float eds[NN];
    __shared__ float red[256];
    int bh = blockIdx.y;
    const float* ed = g_ed + bh * NN;
    int tid = threadIdx.x, warp = tid >> 5, lane = tid & 31;

    float lm = -1e30f;
    for (int j = tid; j < NN; j += 256) { float v = ed[j]; eds[j] = v; lm = fmaxf(lm, v); }
    red[tid] = lm; __syncthreads();
    for (int s = 128; s > 0; s >>= 1) {
        if (tid < s) red[tid] = fmaxf(red[tid], red[tid + s]);
        __syncthreads();
    }
    float maxed = red[0];

    int i = blockIdx.x * 8 + warp;
    unsigned mw = g_adjb[i * 32 + lane];
    float mv = -1e30f;
    #pragma unroll
    for (int k = 0; k < 32; k++)
        if ((mw >> k) & 1u) mv = fmaxf(mv, eds[lane * 32 + k]);
    mv = warpMax(mv);
    if (lane == 0) {
        float es = g_es[bh * NN + i];
        if (mv < -1e29f) { g_A1[bh * NN + i] = 0.f; g_A2[bh * NN + i] = 0.f; }
        else {
            float t = es + mv;
            float m = t > 0.f ? t : NEG * t;
            g_A1[bh * NN + i] = __expf(es - m + maxed);
            g_A2[bh * NN + i] = __expf(NEG * (es + maxed) - m);
        }
    }
    if (blockIdx.x == 0) {
        for (int j = tid; j < NN; j += 256) {
            float d = eds[j] - maxed;
            g_E1[bh * NN + j] = __expf(d);
            g_E2[bh * NN + j] = __expf(NEG * d);
        }
    }
}

// ---------------- 5. fused masked-softmax attention aggregation + ELU ----------------
template <int D>
__global__ __launch_bounds__(256) void k_agg(int outid, int H) {
    constexpr int JT = 64;
    constexpr int KD = D / 32;
    __shared__ float hs[JT * D];
    __shared__ float eds[JT], e1s[JT], e2s[JT];
    __shared__ unsigned ms[32][2];

    int tid = threadIdx.x, warp = tid >> 5, lane = tid & 31;
    int bh = blockIdx.y;
    int b = bh / H, head = bh - b * H;
    int hoff = head * D;
    int i0 = blockIdx.x * 32;

    float esr[4], A1r[4], A2r[4], sumr[4];
    float acc[4][KD];
    #pragma unroll
    for (int r = 0; r < 4; r++) {
        int i = i0 + warp * 4 + r;
        esr[r] = g_es[bh * NN + i];
        A1r[r] = g_A1[bh * NN + i];
        A2r[r] = g_A2[bh * NN + i];
        sumr[r] = 0.f;
        #pragma unroll
        for (int k = 0; k < KD; k++) acc[r][k] = 0.f;
    }

    for (int jc = 0; jc < NN; jc += JT) {
        __syncthreads();
        for (int idx = tid; idx < JT * D; idx += 256) {
            int j = idx / D, c = idx - j * D;
            hs[idx] = g_h[(b * NN + jc + j) * HIDD + hoff + c];
        }
        if (tid < JT)            eds[tid]            = g_ed[bh * NN + jc + tid];
        else if (tid < 2 * JT)   e1s[tid - JT]       = g_E1[bh * NN + jc + tid - JT];
        else if (tid < 3 * JT)   e2s[tid - 2 * JT]   = g_E2[bh * NN + jc + tid - 2 * JT];
        else { // 64 threads: 32 rows x 2 mask words
            int idx = tid - 192;
            ms[idx >> 1][idx & 1] = g_adjb[(i0 + (idx >> 1)) * 32 + (jc >> 5) + (idx & 1)];
        }
        __syncthreads();

        #pragma unroll
        for (int r = 0; r < 4; r++) {
            int rl = warp * 4 + r;
            #pragma unroll
            for (int js = 0; js < JT / 32; js++) {
                unsigned mw = ms[rl][js];
                int j = js * 32 + lane;
                float w = 0.f;
                if ((mw >> lane) & 1u) {
                    float t = esr[r] + eds[j];
                    w = t > 0.f ? A1r[r] * e1s[j] : A2r[r] * e2s[j];
                }
                sumr[r] += w;
                #pragma unroll 8
                for (int s = 0; s < 32; s++) {
                    float ws = __shfl_sync(0xffffffffu, w, s);
                    if (ws != 0.f) {
                        int jj = js * 32 + s;
                        #pragma unroll
                        for (int k = 0; k < KD; k++)
                            acc[r][k] += ws * hs[jj * D + lane + k * 32];
                    }
                }
            }
        }
    }

    float* out = bufsel(outid);
    #pragma unroll
    for (int r = 0; r < 4; r++) {
        float tot = warpSum(sumr[r]);
        float inv = (tot > 0.f) ? (1.f / tot) : 0.f;
        int i = i0 + warp * 4 + r;
        float* o = out + (b * NN + i) * HIDD + hoff;
        #pragma unroll
        for (int k = 0; k < KD; k++) o[lane + k * 32] = eluf(acc[r][k] * inv);
    }
}

// ---------------- 6. partial column sums for pooling (deterministic) ----------------
__global__ void k_pool(int srcid, int slot) {
    // grid (B, 8), block 96
    int b = blockIdx.x, ch = blockIdx.y, col = threadIdx.x;
    const float* p = bufsel(srcid) + (b * NN + ch * 128) * HIDD + col;
    float s = 0.f;
    #pragma unroll 8
    for (int n = 0; n < 128; n++) s += p[n * HIDD];
    g_pool[((slot * 8 + ch) * BB + b) * HIDD + col] = s;
}

// ---------------- 7. gate MLP ----------------
__global__ void k_gates(const float* __restrict__ w1, const float* __restrict__ b1,
                        const float* __restrict__ w2, const float* __restrict__ b2)
{
    __shared__ float pool[2 * HIDD];
    __shared__ float hid[48];
    int b = blockIdx.x, tid = threadIdx.x;
    if (tid < 192) {
        int slot = tid < 96 ? 0 : 1;
        int col = tid < 96 ? tid : tid - 96;
        float s = 0.f;
        #pragma unroll
        for (int c = 0; c < 8; c++) s += g_pool[((slot * 8 + c) * BB + b) * HIDD + col];
        pool[tid] = s * (1.f / NN);
    }
    __syncthreads();
    if (tid < 48) {
        float s = b1[tid];
        #pragma unroll 4
        for (int d = 0; d < 192; d++) s += pool[d] * w1[d * 48 + tid];
        hid[tid] = eluf(s);
    }
    __syncthreads();
    if (tid < 2) {
        float s = b2[tid];
        #pragma unroll
        for (int d = 0; d < 48; d++) s += hid[d] * w2[d * 2 + tid];
        g_gates[b * 2 + tid] = 1.f / (1.f + __expf(-s));
    }
}

// ---------------- 8. final projection + output ----------------
__global__ void k_final(const float* __restrict__ proj_w, const float* __restrict__ proj_b,
                        float* __restrict__ out)
{
    __shared__ float gt[288];
    int b = blockIdx.x, tid = threadIdx.x;   // 288 threads
    if (tid < 288) {
        int slot = 2 + tid / 96;             // slots 2,3,4 = x3,x4,x5
        int col = tid % 96;
        float s = 0.f;
        #pragma unroll
        for (int c = 0; c < 8; c++) s += g_pool[((slot * 8 + c) * BB + b) * HIDD + col];
        gt[tid] = s * (1.f / NN);
    }
    __syncthreads();
    if (tid < 128) {
        float s = proj_b[tid];
        #pragma unroll 4
        for (int d = 0; d < 288; d++) s += gt[d] * proj_w[d * 128 + tid];
        out[b * 128 + tid] = eluf(s);
    }
    if (tid == 128) {
        out[BB * 128 + b]      = g_gates[b * 2];       // w_t
        out[BB * 128 + BB + b] = g_gates[b * 2 + 1];   // w_r
    }
}

// ---------------- launch ----------------
extern "C" void kernel_launch(void* const* d_in, const int* in_sizes, int n_in,
                              void* d_out, int out_size)
{
    const float* x      = (const float*)d_in[0];
    const int*   adj    = (const int*)  d_in[1];
    const float* ln_g   = (const float*)d_in[2];
    const float* ln_b   = (const float*)d_in[3];
    const float* pre_w  = (const float*)d_in[4];
    const float* pre_b  = (const float*)d_in[5];
    const float* g1_w   = (const float*)d_in[6];
    const float* g1_as  = (const float*)d_in[7];
    const float* g1_ad  = (const float*)d_in[8];
    const float* g2_w   = (const float*)d_in[9];
    const float* g2_as  = (const float*)d_in[10];
    const float* g2_ad  = (const float*)d_in[11];
    const float* g3_w   = (const float*)d_in[12];
    const float* g3_as  = (const float*)d_in[13];
    const float* g3_ad  = (const float*)d_in[14];
    const float* g4_w   = (const float*)d_in[15];
    const float* g4_as  = (const float*)d_in[16];
    const float* g4_ad  = (const float*)d_in[17];
    const float* g5_w   = (const float*)d_in[18];
    const float* g5_as  = (const float*)d_in[19];
    const float* g5_ad  = (const float*)d_in[20];
    const float* gate_w1= (const float*)d_in[21];
    const float* gate_b1= (const float*)d_in[22];
    const float* gate_w2= (const float*)d_in[23];
    const float* gate_b2= (const float*)d_in[24];
    const float* proj_w = (const float*)d_in[25];
    const float* proj_b = (const float*)d_in[26];
    float* out = (float*)d_out;

    k_adjbits<<<4096, 256>>>(adj);
    k_ln_pre<<<BB * NN / 8, 256>>>(x, ln_g, ln_b, pre_w, pre_b);

    // gat1 (x0 -> x1): H=3, D=32, concat
    k_gemm_h<<<BB * NN / 8, 256>>>(0, 0, 0, 0, 0, g1_w, g1_as, g1_ad, 3);
    k_prep<<<dim3(NN / 8, BB * 3), 256>>>();
    k_agg<32><<<dim3(NN / 32, BB * 3), 256>>>(1, 3);

    // gat2 (x1 -> x2): H=1, D=96
    k_gemm_h<<<BB * NN / 8, 256>>>(1, 0, 0, 0, 0, g2_w, g2_as, g2_ad, 1);
    k_prep<<<dim3(NN / 8, BB), 256>>>();
    k_agg<96><<<dim3(NN / 32, BB), 256>>>(2, 1);

    // gates from pooled means of x1, x2
    k_pool<<<dim3(BB, 8), 96>>>(1, 0);
    k_pool<<<dim3(BB, 8), 96>>>(2, 1);
    k_gates<<<BB, 256>>>(gate_w1, gate_b1, gate_w2, gate_b2);

    // gat4 on td_in = (1-wt)x1 + wt x2 -> x4
    k_gemm_h<<<BB * NN / 8, 256>>>(1, 2, 0, 1, 0, g4_w, g4_as, g4_ad, 1);
    k_prep<<<dim3(NN / 8, BB), 256>>>();
    k_agg<96><<<dim3(NN / 32, BB), 256>>>(4, 1);

    // gat5 on ra_in = (1-wr)x1 + wr x2 -> x5
    k_gemm_h<<<BB * NN / 8, 256>>>(1, 2, 0, 1, 1, g5_w, g5_as, g5_ad, 1);
    k_prep<<<dim3(NN / 8, BB), 256>>>();
    k_agg<96><<<dim3(NN / 32, BB), 256>>>(5, 1);

    // gat3 on stage_in = x2 + 0.5*(wt x4 + wr x5) -> x3
    k_gemm_h<<<BB * NN / 8, 256>>>(2, 4, 5, 2, 0, g3_w, g3_as, g3_ad, 1);
    k_prep<<<dim3(NN / 8, BB), 256>>>();
    k_agg<96><<<dim3(NN / 32, BB), 256>>>(3, 1);

    // pooled means of x3, x4, x5 + final projection + gate outputs
    k_pool<<<dim3(BB, 8), 96>>>(3, 2);
    k_pool<<<dim3(BB, 8), 96>>>(4, 3);
    k_pool<<<dim3(BB, 8), 96>>>(5, 4);
    k_final<<<BB, 288>>>(proj_w, proj_b, out);
}

// round 2
// speedup vs baseline: 2.4299x; 2.4299x over previous
#include <cuda_runtime.h>
#include <math.h>

// ---------------- problem constants ----------------
#define BB   8
#define NN   1024
#define IND  64
#define HIDD 96
#define MAXH 3
#define NEG  0.2f

// ---------------- scratch (device globals, no allocation) ----------------
__device__ float    g_x[6][BB * NN * HIDD];        // x0..x5
__device__ float    g_h [BB * NN * HIDD];          // current layer h = in @ W
__device__ float    g_es[BB * MAXH * NN];
__device__ float    g_ed[BB * MAXH * NN];
__device__ float    g_A1[BB * MAXH * NN];
__device__ float    g_A2[BB * MAXH * NN];
__device__ float    g_E1[BB * MAXH * NN];
__device__ float    g_E2[BB * MAXH * NN];
__device__ unsigned g_adjb[NN * NN / 32];          // adjacency bitmask
__device__ float    g_gates[BB * 2];
__device__ float    g_pool[5 * 8 * BB * HIDD];     // [slot][chunk][b][col] partial sums
// partial attention outputs: [slot = split*24 + bh][N][96], plus partial row sums
__device__ float    g_pacc[4 * 24 * NN * 96];
__device__ float    g_psum[4 * 24 * NN];

// ---------------- helpers ----------------
__device__ __forceinline__ float warpSum(float v) {
    #pragma unroll
    for (int o = 16; o; o >>= 1) v += __shfl_xor_sync(0xffffffffu, v, o);
    return v;
}
__device__ __forceinline__ float warpMax(float v) {
    #pragma unroll
    for (int o = 16; o; o >>= 1) v = fmaxf(v, __shfl_xor_sync(0xffffffffu, v, o));
    return v;
}
__device__ __forceinline__ float eluf(float x) { return x > 0.f ? x : expm1f(x); }
__device__ __forceinline__ float* bufsel(int id) { return g_x[id]; }

// packed f32x2 helpers (FFMA2 path, sm_103a)
__device__ __forceinline__ void ffma2(unsigned long long& d, unsigned long long a,
                                      unsigned long long b) {
    asm("fma.rn.f32x2 %0, %1, %2, %0;" : "+l"(d) : "l"(a), "l"(b));
}
__device__ __forceinline__ unsigned long long pack2(float x, float y) {
    unsigned long long r;
    asm("mov.b64 %0, {%1, %2};" : "=l"(r) : "f"(x), "f"(y));
    return r;
}
__device__ __forceinline__ void unpack2(unsigned long long v, float& x, float& y) {
    asm("mov.b64 {%0, %1}, %2;" : "=f"(x), "=f"(y) : "l"(v));
}

// ---------------- 1. adjacency -> bitmask ----------------
__global__ void k_adjbits(const int* __restrict__ adj) {
    int gw   = (blockIdx.x * blockDim.x + threadIdx.x) >> 5;
    int lane = threadIdx.x & 31;
    unsigned m = __ballot_sync(0xffffffffu, adj[gw * 32 + lane] > 0);
    if (lane == 0) g_adjb[gw] = m;
}

// ---------------- 2. LayerNorm + pre Linear + ELU -> x0 ----------------
__global__ __launch_bounds__(256) void k_ln_pre(
    const float* __restrict__ x, const float* __restrict__ ln_g,
    const float* __restrict__ ln_b, const float* __restrict__ W,
    const float* __restrict__ bias)
{
    __shared__ float Ws[IND * HIDD];
    __shared__ float xs[8][IND];
    int tid = threadIdx.x, warp = tid >> 5, lane = tid & 31;
    for (int i = tid; i < IND * HIDD; i += 256) Ws[i] = W[i];

    int row = blockIdx.x * 8 + warp;
    const float* xr = x + row * IND;
    float v0 = xr[lane], v1 = xr[lane + 32];
    float mu = warpSum(v0 + v1) * (1.f / IND);
    float d0 = v0 - mu, d1 = v1 - mu;
    float var = warpSum(d0 * d0 + d1 * d1) * (1.f / IND);
    float rs = rsqrtf(var + 1e-5f);
    xs[warp][lane]      = d0 * rs * ln_g[lane]      + ln_b[lane];
    xs[warp][lane + 32] = d1 * rs * ln_g[lane + 32] + ln_b[lane + 32];
    __syncthreads();

    float a0 = bias[lane], a1 = bias[lane + 32], a2 = bias[lane + 64];
    #pragma unroll
    for (int d = 0; d < IND; d++) {
        float xv = xs[warp][d];
        a0 += xv * Ws[d * HIDD + lane];
        a1 += xv * Ws[d * HIDD + lane + 32];
        a2 += xv * Ws[d * HIDD + lane + 64];
    }
    float* o = g_x[0] + row * HIDD;
    o[lane] = eluf(a0); o[lane + 32] = eluf(a1); o[lane + 64] = eluf(a2);
}

// ---------------- 3. h = mix(x) @ W, plus es/ed per head ----------------
__global__ __launch_bounds__(256) void k_gemm_h(
    int ia, int ib, int ic, int mode, int gidx,
    const float* __restrict__ W, const float* __restrict__ a_src,
    const float* __restrict__ a_dst, int H)
{
    __shared__ float Ws[HIDD * HIDD];
    __shared__ float ins[8][HIDD];
    int tid = threadIdx.x, warp = tid >> 5, lane = tid & 31;
    for (int i = tid; i < HIDD * HIDD; i += 256) Ws[i] = W[i];

    int row = blockIdx.x * 8 + warp;
    int b = row >> 10;

    float c_a = 1.f, c_b = 0.f, c_c = 0.f;
    if (mode == 1) { float g = g_gates[b * 2 + gidx]; c_a = 1.f - g; c_b = g; }
    else if (mode == 2) {
        float wt = g_gates[b * 2], wr = g_gates[b * 2 + 1];
        c_b = 0.5f * wt; c_c = 0.5f * wr;
    }
    const float* A = bufsel(ia) + row * HIDD;
    const float* Bp = bufsel(ib) + row * HIDD;
    const float* Cp = bufsel(ic) + row * HIDD;
    #pragma unroll
    for (int k = 0; k < 3; k++) {
        int c = lane + 32 * k;
        float v = c_a * A[c];
        if (mode >= 1) v += c_b * Bp[c];
        if (mode == 2) v += c_c * Cp[c];
        ins[warp][c] = v;
    }
    __syncthreads();

    float a0 = 0.f, a1 = 0.f, a2 = 0.f;
    #pragma unroll
    for (int d = 0; d < HIDD; d++) {
        float xv = ins[warp][d];
        a0 += xv * Ws[d * HIDD + lane];
        a1 += xv * Ws[d * HIDD + lane + 32];
        a2 += xv * Ws[d * HIDD + lane + 64];
    }
    float* hp = g_h + row * HIDD;
    hp[lane] = a0; hp[lane + 32] = a1; hp[lane + 64] = a2;

    int n = row & (NN - 1);
    if (H == 1) {
        float ps = a0 * a_src[lane] + a1 * a_src[lane + 32] + a2 * a_src[lane + 64];
        float pd = a0 * a_dst[lane] + a1 * a_dst[lane + 32] + a2 * a_dst[lane + 64];
        ps = warpSum(ps); pd = warpSum(pd);
        if (lane == 0) { g_es[b * NN + n] = ps; g_ed[b * NN + n] = pd; }
    } else {
        float s0 = warpSum(a0 * a_src[lane]);
        float s1 = warpSum(a1 * a_src[32 + lane]);
        float s2 = warpSum(a2 * a_src[64 + lane]);
        float e0 = warpSum(a0 * a_dst[lane]);
        float e1 = warpSum(a1 * a_dst[32 + lane]);
        float e2 = warpSum(a2 * a_dst[64 + lane]);
        if (lane == 0) {
            g_es[(b * 3 + 0) * NN + n] = s0; g_ed[(b * 3 + 0) * NN + n] = e0;
            g_es[(b * 3 + 1) * NN + n] = s1; g_ed[(b * 3 + 1) * NN + n] = e1;
            g_es[(b * 3 + 2) * NN + n] = s2; g_ed[(b * 3 + 2) * NN + n] = e2;
        }
    }
}

// ---------------- 4. per-row masked max + exp factor precompute ----------------
// padded eds (j -> j + (j>>5)) makes the per-row bit-scan conflict-free.
__global__ __launch_bounds__(256) void k_prep() {
    __shared__ float eds[NN + NN / 32];
    __shared__ float red[8];
    int bh = blockIdx.y;
    const float* ed = g_ed + bh * NN;
    int tid = threadIdx.x, warp = tid >> 5, lane = tid & 31;

    float lm = -1e30f;
    for (int j = tid; j < NN; j += 256) {
        float v = ed[j];
        eds[j + (j >> 5)] = v;
        lm = fmaxf(lm, v);
    }
    lm = warpMax(lm);
    if (lane == 0) red[warp] = lm;
    __syncthreads();
    float maxed = fmaxf(fmaxf(fmaxf(red[0], red[1]), fmaxf(red[2], red[3])),
                        fmaxf(fmaxf(red[4], red[5]), fmaxf(red[6], red[7])));

    #pragma unroll
    for (int r = 0; r < 4; r++) {
        int i = blockIdx.x * 32 + warp * 4 + r;
        unsigned mw = g_adjb[i * 32 + lane];
        float mv = -1e30f;
        int base = lane * 33;   // lane*32 + pad(lane)
        #pragma unroll
        for (int k = 0; k < 32; k++)
            if ((mw >> k) & 1u) mv = fmaxf(mv, eds[base + k]);
        mv = warpMax(mv);
        if (lane == 0) {
            float es = g_es[bh * NN + i];
            if (mv < -1e29f) { g_A1[bh * NN + i] = 0.f; g_A2[bh * NN + i] = 0.f; }
            else {
                float t = es + mv;
                float m = t > 0.f ? t : NEG * t;
                g_A1[bh * NN + i] = __expf(es - m + maxed);
                g_A2[bh * NN + i] = __expf(NEG * (es + maxed) - m);
            }
        }
    }
    if (blockIdx.x == 0) {
        for (int j = tid; j < NN; j += 256) {
            float d = eds[j + (j >> 5)] - maxed;
            g_E1[bh * NN + j] = __expf(d);
            g_E2[bh * NN + j] = __expf(NEG * d);
        }
    }
}

// ---------------- 5. fused attention aggregation (partials, FFMA2) ----------------
// block: 256 thr = 8 warps, warp owns 8 rows, block owns 64 rows.
// grid: (NN/64, S, B*H); each y-slice handles NN/S of the j range.
template <int D, int S>
__global__ __launch_bounds__(256) void k_agg(int H) {
    constexpr int KD = D / 32;
    constexpr int RW = 8;            // rows per warp
    __shared__ float hs[64 * D];
    __shared__ float eds[64], e1s[64], e2s[64];
    __shared__ unsigned ms[64][2];
    __shared__ float2 ws2[8][RW / 2][64];   // [warp][rowpair][j]

    int tid = threadIdx.x, warp = tid >> 5, lane = tid & 31;
    int bh = blockIdx.z;
    int b = bh / H, head = bh - b * H;
    int hoff = head * D;
    int i0 = blockIdx.x * 64;
    int row0 = i0 + warp * RW;
    int j0 = blockIdx.y * (NN / S);

    float esr[RW], A1r[RW], A2r[RW], sumr[RW];
    unsigned long long acc2[RW / 2][KD];
    #pragma unroll
    for (int r = 0; r < RW; r++) {
        int i = row0 + r;
        esr[r] = g_es[bh * NN + i];
        A1r[r] = g_A1[bh * NN + i];
        A2r[r] = g_A2[bh * NN + i];
        sumr[r] = 0.f;
    }
    #pragma unroll
    for (int p = 0; p < RW / 2; p++)
        #pragma unroll
        for (int k = 0; k < KD; k++) acc2[p][k] = 0ull;

    for (int jc = j0; jc < j0 + NN / S; jc += 64) {
        __syncthreads();
        for (int idx = tid; idx < 64 * D; idx += 256) {
            int j = idx / D, c = idx - j * D;
            hs[idx] = g_h[(b * NN + jc + j) * HIDD + hoff + c];
        }
        if (tid < 64)            eds[tid]       = g_ed[bh * NN + jc + tid];
        else if (tid < 128)      e1s[tid - 64]  = g_E1[bh * NN + jc + tid - 64];
        else if (tid < 192)      e2s[tid - 128] = g_E2[bh * NN + jc + tid - 128];
        else {
            int x = tid - 192;
            ms[x][0] = g_adjb[(i0 + x) * 32 + (jc >> 5)];
            ms[x][1] = g_adjb[(i0 + x) * 32 + (jc >> 5) + 1];
        }
        __syncthreads();

        #pragma unroll
        for (int js = 0; js < 2; js++) {
            int j = js * 32 + lane;
            float edv = eds[j], e1v = e1s[j], e2v = e2s[j];
            float wloc[RW];
            #pragma unroll
            for (int r = 0; r < RW; r++) {
                unsigned mw = ms[warp * RW + r][js];
                float t = esr[r] + edv;
                float w = (t > 0.f) ? A1r[r] * e1v : A2r[r] * e2v;
                w = ((mw >> lane) & 1u) ? w : 0.f;
                sumr[r] += w;
                wloc[r] = w;
            }
            #pragma unroll
            for (int p = 0; p < RW / 2; p++)
                ws2[warp][p][j] = make_float2(wloc[2 * p], wloc[2 * p + 1]);
            __syncwarp();

            #pragma unroll 4
            for (int s = 0; s < 32; s++) {
                int jj = js * 32 + s;
                float hvf[KD];
                unsigned long long hv2[KD];
                #pragma unroll
                for (int k = 0; k < KD; k++) {
                    hvf[k] = hs[jj * D + lane + 32 * k];
                    hv2[k] = pack2(hvf[k], hvf[k]);
                }
                #pragma unroll
                for (int p = 0; p < RW / 2; p++) {
                    unsigned long long w2 =
                        *reinterpret_cast<const unsigned long long*>(&ws2[warp][p][jj]);
                    #pragma unroll
                    for (int k = 0; k < KD; k++) ffma2(acc2[p][k], w2, hv2[k]);
                }
            }
            __syncwarp();
        }
    }

    int slot = blockIdx.y * 24 + bh;
    float* pa = g_pacc + (size_t)slot * NN * 96;
    #pragma unroll
    for (int p = 0; p < RW / 2; p++) {
        float alo[KD], ahi[KD];
        #pragma unroll
        for (int k = 0; k < KD; k++) unpack2(acc2[p][k], alo[k], ahi[k]);
        int r0 = 2 * p, r1 = 2 * p + 1;
        float t0 = warpSum(sumr[r0]);
        float t1 = warpSum(sumr[r1]);
        int i_0 = row0 + r0, i_1 = row0 + r1;
        if (lane == 0) {
            g_psum[slot * NN + i_0] = t0;
            g_psum[slot * NN + i_1] = t1;
        }
        #pragma unroll
        for (int k = 0; k < KD; k++) {
            pa[i_0 * 96 + lane + 32 * k] = alo[k];
            pa[i_1 * 96 + lane + 32 * k] = ahi[k];
        }
    }
}

// ---------------- 5b. combine partials: normalize + ELU -> x[outid] ----------------
template <int D, int S>
__global__ __launch_bounds__(256) void k_comb(int outid, int H) {
    constexpr int KD = D / 32;
    int tid = threadIdx.x, warp = tid >> 5, lane = tid & 31;
    int bh = blockIdx.y;
    int b = bh / H, head = bh - b * H;
    int hoff = head * D;
    int i = blockIdx.x * 8 + warp;

    float acc[KD];
    #pragma unroll
    for (int k = 0; k < KD; k++) acc[k] = 0.f;
    float tot = 0.f;
    #pragma unroll
    for (int sp = 0; sp < S; sp++) {
        int slot = sp * 24 + bh;
        tot += g_psum[slot * NN + i];
        const float* pa = g_pacc + (size_t)slot * NN * 96 + i * 96;
        #pragma unroll
        for (int k = 0; k < KD; k++) acc[k] += pa[lane + 32 * k];
    }
    float inv = (tot > 0.f) ? (1.f / tot) : 0.f;
    float* o = bufsel(outid) + (b * NN + i) * HIDD + hoff;
    #pragma unroll
    for (int k = 0; k < KD; k++) o[lane + 32 * k] = eluf(acc[k] * inv);
}

// ---------------- 6. partial column sums for pooling ----------------
__global__ void k_pool(int srcid, int slot) {
    int b = blockIdx.x, ch = blockIdx.y, col = threadIdx.x;
    const float* p = bufsel(srcid) + (b * NN + ch * 128) * HIDD + col;
    float s = 0.f;
    #pragma unroll 8
    for (int n = 0; n < 128; n++) s += p[n * HIDD];
    g_pool[((slot * 8 + ch) * BB + b) * HIDD + col] = s;
}

// ---------------- 7. gate MLP ----------------
__global__ void k_gates(const float* __restrict__ w1, const float* __restrict__ b1,
                        const float* __restrict__ w2, const float* __restrict__ b2)
{
    __shared__ float pool[2 * HIDD];
    __shared__ float hid[48];
    int b = blockIdx.x, tid = threadIdx.x;
    if (tid < 192) {
        int slot = tid < 96 ? 0 : 1;
        int col = tid < 96 ? tid : tid - 96;
        float s = 0.f;
        #pragma unroll
        for (int c = 0; c < 8; c++) s += g_pool[((slot * 8 + c) * BB + b) * HIDD + col];
        pool[tid] = s * (1.f / NN);
    }
    __syncthreads();
    if (tid < 48) {
        float s = b1[tid];
        #pragma unroll 4
        for (int d = 0; d < 192; d++) s += pool[d] * w1[d * 48 + tid];
        hid[tid] = eluf(s);
    }
    __syncthreads();
    if (tid < 2) {
        float s = b2[tid];
        #pragma unroll
        for (int d = 0; d < 48; d++) s += hid[d] * w2[d * 2 + tid];
        g_gates[b * 2 + tid] = 1.f / (1.f + __expf(-s));
    }
}

// ---------------- 8. final projection + output ----------------
__global__ void k_final(const float* __restrict__ proj_w, const float* __restrict__ proj_b,
                        float* __restrict__ out)
{
    __shared__ float gt[288];
    int b = blockIdx.x, tid = threadIdx.x;
    if (tid < 288) {
        int slot = 2 + tid / 96;
        int col = tid % 96;
        float s = 0.f;
        #pragma unroll
        for (int c = 0; c < 8; c++) s += g_pool[((slot * 8 + c) * BB + b) * HIDD + col];
        gt[tid] = s * (1.f / NN);
    }
    __syncthreads();
    if (tid < 128) {
        float s = proj_b[tid];
        #pragma unroll 4
        for (int d = 0; d < 288; d++) s += gt[d] * proj_w[d * 128 + tid];
        out[b * 128 + tid] = eluf(s);
    }
    if (tid == 128) {
        out[BB * 128 + b]      = g_gates[b * 2];
        out[BB * 128 + BB + b] = g_gates[b * 2 + 1];
    }
}

// ---------------- launch ----------------
extern "C" void kernel_launch(void* const* d_in, const int* in_sizes, int n_in,
                              void* d_out, int out_size)
{
    const float* x      = (const float*)d_in[0];
    const int*   adj    = (const int*)  d_in[1];
    const float* ln_g   = (const float*)d_in[2];
    const float* ln_b   = (const float*)d_in[3];
    const float* pre_w  = (const float*)d_in[4];
    const float* pre_b  = (const float*)d_in[5];
    const float* g1_w   = (const float*)d_in[6];
    const float* g1_as  = (const float*)d_in[7];
    const float* g1_ad  = (const float*)d_in[8];
    const float* g2_w   = (const float*)d_in[9];
    const float* g2_as  = (const float*)d_in[10];
    const float* g2_ad  = (const float*)d_in[11];
    const float* g3_w   = (const float*)d_in[12];
    const float* g3_as  = (const float*)d_in[13];
    const float* g3_ad  = (const float*)d_in[14];
    const float* g4_w   = (const float*)d_in[15];
    const float* g4_as  = (const float*)d_in[16];
    const float* g4_ad  = (const float*)d_in[17];
    const float* g5_w   = (const float*)d_in[18];
    const float* g5_as  = (const float*)d_in[19];
    const float* g5_ad  = (const float*)d_in[20];
    const float* gate_w1= (const float*)d_in[21];
    const float* gate_b1= (const float*)d_in[22];
    const float* gate_w2= (const float*)d_in[23];
    const float* gate_b2= (const float*)d_in[24];
    const float* proj_w = (const float*)d_in[25];
    const float* proj_b = (const float*)d_in[26];
    float* out = (float*)d_out;

    k_adjbits<<<4096, 256>>>(adj);
    k_ln_pre<<<BB * NN / 8, 256>>>(x, ln_g, ln_b, pre_w, pre_b);

    // gat1 (x0 -> x1): H=3, D=32, concat
    k_gemm_h<<<BB * NN / 8, 256>>>(0, 0, 0, 0, 0, g1_w, g1_as, g1_ad, 3);
    k_prep<<<dim3(NN / 32, BB * 3), 256>>>();
    k_agg<32, 2><<<dim3(NN / 64, 2, BB * 3), 256>>>(3);
    k_comb<32, 2><<<dim3(NN / 8, BB * 3), 256>>>(1, 3);

    // gat2 (x1 -> x2): H=1, D=96
    k_gemm_h<<<BB * NN / 8, 256>>>(1, 0, 0, 0, 0, g2_w, g2_as, g2_ad, 1);
    k_prep<<<dim3(NN / 32, BB), 256>>>();
    k_agg<96, 4><<<dim3(NN / 64, 4, BB), 256>>>(1);
    k_comb<96, 4><<<dim3(NN / 8, BB), 256>>>(2, 1);

    // gates from pooled means of x1, x2
    k_pool<<<dim3(BB, 8), 96>>>(1, 0);
    k_pool<<<dim3(BB, 8), 96>>>(2, 1);
    k_gates<<<BB, 256>>>(gate_w1, gate_b1, gate_w2, gate_b2);

    // gat4 on td_in = (1-wt)x1 + wt x2 -> x4
    k_gemm_h<<<BB * NN / 8, 256>>>(1, 2, 0, 1, 0, g4_w, g4_as, g4_ad, 1);
    k_prep<<<dim3(NN / 32, BB), 256>>>();
    k_agg<96, 4><<<dim3(NN / 64, 4, BB), 256>>>(1);
    k_comb<96, 4><<<dim3(NN / 8, BB), 256>>>(4, 1);

    // gat5 on ra_in = (1-wr)x1 + wr x2 -> x5
    k_gemm_h<<<BB * NN / 8, 256>>>(1, 2, 0, 1, 1, g5_w, g5_as, g5_ad, 1);
    k_prep<<<dim3(NN / 32, BB), 256>>>();
    k_agg<96, 4><<<dim3(NN / 64, 4, BB), 256>>>(1);
    k_comb<96, 4><<<dim3(NN / 8, BB), 256>>>(5, 1);

    // gat3 on stage_in = x2 + 0.5*(wt x4 + wr x5) -> x3
    k_gemm_h<<<BB * NN / 8, 256>>>(2, 4, 5, 2, 0, g3_w, g3_as, g3_ad, 1);
    k_prep<<<dim3(NN / 32, BB), 256>>>();
    k_agg<96, 4><<<dim3(NN / 64, 4, BB), 256>>>(1);
    k_comb<96, 4><<<dim3(NN / 8, BB), 256>>>(3, 1);

    // pooled means of x3, x4, x5 + final projection + gate outputs
    k_pool<<<dim3(BB, 8), 96>>>(3, 2);
    k_pool<<<dim3(BB, 8), 96>>>(4, 3);
    k_pool<<<dim3(BB, 8), 96>>>(5, 4);
    k_final<<<BB, 288>>>(proj_w, proj_b, out);
}

// round 4
// speedup vs baseline: 2.8454x; 1.1710x over previous
#include <cuda_runtime.h>
#include <math.h>
#include <stdint.h>

// ---------------- problem constants ----------------
#define BB   8
#define NN   1024
#define IND  64
#define HIDD 96
#define NEG  0.2f

// ---------------- scratch (device globals) ----------------
__device__ float    g_x[6][BB * NN * HIDD];        // x0..x5
__device__ float    g_hT[BB * HIDD * NN];          // h transposed: [b][col][n]
__device__ float    g_es[BB * 3 * NN];
__device__ float    g_ed[BB * 3 * NN];
__device__ float    g_A1[BB * 3 * NN];
__device__ float    g_A2[BB * 3 * NN];
__device__ float    g_E1[BB * 3 * NN];
__device__ float    g_E2[BB * 3 * NN];
__device__ unsigned g_adjb[NN * NN / 32];
__device__ float    g_gates[BB * 2];
__device__ float    g_pool[5 * 8 * BB * HIDD];

// ---------------- helpers ----------------
__device__ __forceinline__ float warpSum(float v) {
    #pragma unroll
    for (int o = 16; o; o >>= 1) v += __shfl_xor_sync(0xffffffffu, v, o);
    return v;
}
__device__ __forceinline__ float warpMax(float v) {
    #pragma unroll
    for (int o = 16; o; o >>= 1) v = fmaxf(v, __shfl_xor_sync(0xffffffffu, v, o));
    return v;
}
__device__ __forceinline__ float eluf(float x) { return x > 0.f ? x : expm1f(x); }
__device__ __forceinline__ float* bufsel(int id) { return g_x[id]; }

__device__ __forceinline__ uint32_t to_tf32(float f) {
    uint32_t u;
    asm("cvt.rna.tf32.f32 %0, %1;" : "=r"(u) : "f"(f));
    return u;
}
__device__ __forceinline__ void mma_tf32(float* c, uint32_t a0, uint32_t a1,
                                         uint32_t a2, uint32_t a3,
                                         uint32_t b0, uint32_t b1) {
    asm volatile(
        "mma.sync.aligned.m16n8k8.row.col.f32.tf32.tf32.f32 "
        "{%0,%1,%2,%3}, {%4,%5,%6,%7}, {%8,%9}, {%0,%1,%2,%3};"
        : "+f"(c[0]), "+f"(c[1]), "+f"(c[2]), "+f"(c[3])
        : "r"(a0), "r"(a1), "r"(a2), "r"(a3), "r"(b0), "r"(b1));
}

// ---------------- 1. adjacency -> bitmask ----------------
__global__ void k_adjbits(const int* __restrict__ adj) {
    int gw   = (blockIdx.x * blockDim.x + threadIdx.x) >> 5;
    int lane = threadIdx.x & 31;
    unsigned m = __ballot_sync(0xffffffffu, adj[gw * 32 + lane] > 0);
    if (lane == 0) g_adjb[gw] = m;
}

// ---------------- 2. LayerNorm + pre Linear + ELU -> x0 ----------------
__global__ __launch_bounds__(256) void k_ln_pre(
    const float* __restrict__ x, const float* __restrict__ ln_g,
    const float* __restrict__ ln_b, const float* __restrict__ W,
    const float* __restrict__ bias)
{
    __shared__ float Ws[IND * HIDD];
    __shared__ float xs[8][IND];
    int tid = threadIdx.x, warp = tid >> 5, lane = tid & 31;
    for (int i = tid; i < IND * HIDD; i += 256) Ws[i] = W[i];

    int row = blockIdx.x * 8 + warp;
    const float* xr = x + row * IND;
    float v0 = xr[lane], v1 = xr[lane + 32];
    float mu = warpSum(v0 + v1) * (1.f / IND);
    float d0 = v0 - mu, d1 = v1 - mu;
    float var = warpSum(d0 * d0 + d1 * d1) * (1.f / IND);
    float rs = rsqrtf(var + 1e-5f);
    xs[warp][lane]      = d0 * rs * ln_g[lane]      + ln_b[lane];
    xs[warp][lane + 32] = d1 * rs * ln_g[lane + 32] + ln_b[lane + 32];
    __syncthreads();

    float a0 = bias[lane], a1 = bias[lane + 32], a2 = bias[lane + 64];
    #pragma unroll
    for (int d = 0; d < IND; d++) {
        float xv = xs[warp][d];
        a0 += xv * Ws[d * HIDD + lane];
        a1 += xv * Ws[d * HIDD + lane + 32];
        a2 += xv * Ws[d * HIDD + lane + 64];
    }
    float* o = g_x[0] + row * HIDD;
    o[lane] = eluf(a0); o[lane + 32] = eluf(a1); o[lane + 64] = eluf(a2);
}

// ---------------- 3. h = mix(x) @ W -> hT, plus es/ed per head ----------------
__global__ __launch_bounds__(256) void k_gemm_h(
    int ia, int ib, int ic, int mode, int gidx,
    const float* __restrict__ W, const float* __restrict__ a_src,
    const float* __restrict__ a_dst, int H)
{
    __shared__ float Ws[HIDD * HIDD];
    __shared__ float ins[8][HIDD];
    int tid = threadIdx.x, warp = tid >> 5, lane = tid & 31;
    for (int i = tid; i < HIDD * HIDD; i += 256) Ws[i] = W[i];

    int row = blockIdx.x * 8 + warp;
    int b = row >> 10;

    float c_a = 1.f, c_b = 0.f, c_c = 0.f;
    if (mode == 1) { float g = g_gates[b * 2 + gidx]; c_a = 1.f - g; c_b = g; }
    else if (mode == 2) {
        float wt = g_gates[b * 2], wr = g_gates[b * 2 + 1];
        c_b = 0.5f * wt; c_c = 0.5f * wr;
    }
    const float* A  = bufsel(ia) + row * HIDD;
    const float* Bp = bufsel(ib) + row * HIDD;
    const float* Cp = bufsel(ic) + row * HIDD;
    #pragma unroll
    for (int k = 0; k < 3; k++) {
        int c = lane + 32 * k;
        float v = c_a * A[c];
        if (mode >= 1) v += c_b * Bp[c];
        if (mode == 2) v += c_c * Cp[c];
        ins[warp][c] = v;
    }
    __syncthreads();

    float a0 = 0.f, a1 = 0.f, a2 = 0.f;
    #pragma unroll
    for (int d = 0; d < HIDD; d++) {
        float xv = ins[warp][d];
        a0 += xv * Ws[d * HIDD + lane];
        a1 += xv * Ws[d * HIDD + lane + 32];
        a2 += xv * Ws[d * HIDD + lane + 64];
    }
    int n = row & (NN - 1);
    float* hT = g_hT + (size_t)b * HIDD * NN;
    hT[(lane)      * NN + n] = a0;
    hT[(lane + 32) * NN + n] = a1;
    hT[(lane + 64) * NN + n] = a2;

    if (H == 1) {
        float ps = a0 * a_src[lane] + a1 * a_src[lane + 32] + a2 * a_src[lane + 64];
        float pd = a0 * a_dst[lane] + a1 * a_dst[lane + 32] + a2 * a_dst[lane + 64];
        ps = warpSum(ps); pd = warpSum(pd);
        if (lane == 0) { g_es[b * NN + n] = ps; g_ed[b * NN + n] = pd; }
    } else {
        float s0 = warpSum(a0 * a_src[lane]);
        float s1 = warpSum(a1 * a_src[32 + lane]);
        float s2 = warpSum(a2 * a_src[64 + lane]);
        float e0 = warpSum(a0 * a_dst[lane]);
        float e1 = warpSum(a1 * a_dst[32 + lane]);
        float e2 = warpSum(a2 * a_dst[64 + lane]);
        if (lane == 0) {
            g_es[(b * 3 + 0) * NN + n] = s0; g_ed[(b * 3 + 0) * NN + n] = e0;
            g_es[(b * 3 + 1) * NN + n] = s1; g_ed[(b * 3 + 1) * NN + n] = e1;
            g_es[(b * 3 + 2) * NN + n] = s2; g_ed[(b * 3 + 2) * NN + n] = e2;
        }
    }
}

// ---------------- 4. exp factor precompute (O(N), global-max stabilizer) ----------------
__global__ __launch_bounds__(1024) void k_prep2() {
    __shared__ float red[32];
    int bh = blockIdx.x, tid = threadIdx.x;
    float ed = g_ed[bh * NN + tid];
    float m = warpMax(ed);
    if ((tid & 31) == 0) red[tid >> 5] = m;
    __syncthreads();
    if (tid < 32) { float v = red[tid]; v = warpMax(v); if (tid == 0) red[0] = v; }
    __syncthreads();
    float maxed = red[0];
    float d = ed - maxed;
    g_E1[bh * NN + tid] = __expf(d);
    g_E2[bh * NN + tid] = __expf(NEG * d);
    float es = g_es[bh * NN + tid];
    float t = es + maxed;
    float mm = t > 0.f ? t : NEG * t;
    g_A1[bh * NN + tid] = __expf(t - mm);
    g_A2[bh * NN + tid] = __expf(NEG * t - mm);
}

// ---------------- 5. attention aggregation via mma.sync tf32 ----------------
// Computes out^T[D x 64] = H^T (A operand, smem) @ W^T (B operand, registers).
// Block: 256 thr = 8 warps = (mi 0..1) x (ni 0..3). Warp tile: (D/2) x 16.
// grid: (NN/64, B*H).
template <int D>
__global__ __launch_bounds__(256) void k_aggT(int outid, int H) {
    constexpr int MT = D / 16;        // total m-tiles (rows of out^T, i.e. feature dim)
    constexpr int MT_W = MT / 2;      // m-tiles per warp
    constexpr int NT_W = 2;           // n-tiles per warp (8 i each)

    __shared__ uint32_t hs[D * 36];   // tf32 tile [d][j], stride 36 (conflict-free frags)
    __shared__ float es_s[64], A1s[64], A2s[64], invs[64], rsums[64];
    __shared__ float eds[32], e1s[32], e2s[32];
    __shared__ unsigned ms[64];

    int tid = threadIdx.x, wid = tid >> 5, lane = tid & 31;
    int g = lane >> 2, tg = lane & 3;
    int mi = wid >> 2, ni = wid & 3;
    int bh = blockIdx.y, b = bh / H, head = bh - b * H, hoff = head * D;
    int i0 = blockIdx.x * 64;

    const float* hTb = g_hT + ((size_t)b * HIDD + hoff) * NN;

    if (tid < 64) {
        es_s[tid] = g_es[bh * NN + i0 + tid];
        A1s[tid]  = g_A1[bh * NN + i0 + tid];
        A2s[tid]  = g_A2[bh * NN + i0 + tid];
    }
    __syncthreads();

    // per-thread B-side row constants (i = (ni*NT_W+ntl)*8 + g)
    float esb[NT_W], A1b[NT_W], A2b[NT_W], rs[NT_W];
    int ib_loc[NT_W];
    #pragma unroll
    for (int ntl = 0; ntl < NT_W; ntl++) {
        ib_loc[ntl] = (ni * NT_W + ntl) * 8 + g;
        esb[ntl] = es_s[ib_loc[ntl]];
        A1b[ntl] = A1s[ib_loc[ntl]];
        A2b[ntl] = A2s[ib_loc[ntl]];
        rs[ntl] = 0.f;
    }

    float acc[MT_W][NT_W][4];
    #pragma unroll
    for (int m = 0; m < MT_W; m++)
        #pragma unroll
        for (int n = 0; n < NT_W; n++)
            #pragma unroll
            for (int q = 0; q < 4; q++) acc[m][n][q] = 0.f;

    for (int c = 0; c < NN / 32; c++) {
        int j0 = c * 32;
        __syncthreads();
        #pragma unroll
        for (int it = 0; it < D * 32 / 256; it++) {
            int idx = tid + it * 256;
            int d = idx >> 5, jj = idx & 31;
            hs[d * 36 + jj] = to_tf32(hTb[(size_t)d * NN + j0 + jj]);
        }
        if (tid < 32)        eds[tid]       = g_ed[bh * NN + j0 + tid];
        else if (tid < 64)   e1s[tid - 32]  = g_E1[bh * NN + j0 + tid - 32];
        else if (tid < 96)   e2s[tid - 64]  = g_E2[bh * NN + j0 + tid - 64];
        else if (tid < 160)  ms[tid - 96]   = g_adjb[(i0 + tid - 96) * 32 + c];
        __syncthreads();

        unsigned msb[NT_W];
        #pragma unroll
        for (int ntl = 0; ntl < NT_W; ntl++) msb[ntl] = ms[ib_loc[ntl]];

        #pragma unroll
        for (int kt = 0; kt < 4; kt++) {
            int jl = kt * 8 + tg, jh = jl + 4;
            float edl = eds[jl], e1l = e1s[jl], e2l = e2s[jl];
            float edh = eds[jh], e1h = e1s[jh], e2h = e2s[jh];
            uint32_t bf0[NT_W], bf1[NT_W];
            #pragma unroll
            for (int ntl = 0; ntl < NT_W; ntl++) {
                float t0 = esb[ntl] + edl;
                float w0 = (t0 > 0.f) ? A1b[ntl] * e1l : A2b[ntl] * e2l;
                w0 = ((msb[ntl] >> jl) & 1u) ? w0 : 0.f;
                float t1 = esb[ntl] + edh;
                float w1 = (t1 > 0.f) ? A1b[ntl] * e1h : A2b[ntl] * e2h;
                w1 = ((msb[ntl] >> jh) & 1u) ? w1 : 0.f;
                if (mi == 0) rs[ntl] += w0 + w1;
                bf0[ntl] = to_tf32(w0);
                bf1[ntl] = to_tf32(w1);
            }
            #pragma unroll
            for (int mt = 0; mt < MT_W; mt++) {
                int dr = (mi * MT_W + mt) * 16 + g;
                uint32_t a0 = hs[dr * 36 + jl];
                uint32_t a1 = hs[(dr + 8) * 36 + jl];
                uint32_t a2 = hs[dr * 36 + jh];
                uint32_t a3 = hs[(dr + 8) * 36 + jh];
                #pragma unroll
                for (int ntl = 0; ntl < NT_W; ntl++)
                    mma_tf32(acc[mt][ntl], a0, a1, a2, a3, bf0[ntl], bf1[ntl]);
            }
        }
    }

    if (mi == 0) {
        #pragma unroll
        for (int ntl = 0; ntl < NT_W; ntl++) {
            float r = rs[ntl];
            r += __shfl_xor_sync(0xffffffffu, r, 1);
            r += __shfl_xor_sync(0xffffffffu, r, 2);
            if (tg == 0) rsums[ib_loc[ntl]] = r;
        }
    }
    __syncthreads();
    if (tid < 64) {
        float rv = rsums[tid];
        invs[tid] = (rv > 0.f) ? (1.f / rv) : 0.f;
    }
    __syncthreads();

    float* outp = bufsel(outid);
    #pragma unroll
    for (int mt = 0; mt < MT_W; mt++) {
        int d = (mi * MT_W + mt) * 16 + g;
        #pragma unroll
        for (int ntl = 0; ntl < NT_W; ntl++) {
            int iL = (ni * NT_W + ntl) * 8 + tg * 2;
            float inv0 = invs[iL], inv1 = invs[iL + 1];
            size_t r0 = (size_t)(b * NN + i0 + iL) * HIDD + hoff;
            size_t r1 = r0 + HIDD;
            outp[r0 + d]     = eluf(acc[mt][ntl][0] * inv0);
            outp[r1 + d]     = eluf(acc[mt][ntl][1] * inv1);
            outp[r0 + d + 8] = eluf(acc[mt][ntl][2] * inv0);
            outp[r1 + d + 8] = eluf(acc[mt][ntl][3] * inv1);
        }
    }
}

// ---------------- 6. partial column sums for pooling ----------------
__global__ void k_pool(int srcid, int slot) {
    int b = blockIdx.x, ch = blockIdx.y, col = threadIdx.x;
    const float* p = bufsel(srcid) + (b * NN + ch * 128) * HIDD + col;
    float s = 0.f;
    #pragma unroll 8
    for (int n = 0; n < 128; n++) s += p[n * HIDD];
    g_pool[((slot * 8 + ch) * BB + b) * HIDD + col] = s;
}

// ---------------- 7. gate MLP ----------------
__global__ void k_gates(const float* __restrict__ w1, const float* __restrict__ b1,
                        const float* __restrict__ w2, const float* __restrict__ b2)
{
    __shared__ float pool[2 * HIDD];
    __shared__ float hid[48];
    int b = blockIdx.x, tid = threadIdx.x;
    if (tid < 192) {
        int slot = tid < 96 ? 0 : 1;
        int col = tid < 96 ? tid : tid - 96;
        float s = 0.f;
        #pragma unroll
        for (int c = 0; c < 8; c++) s += g_pool[((slot * 8 + c) * BB + b) * HIDD + col];
        pool[tid] = s * (1.f / NN);
    }
    __syncthreads();
    if (tid < 48) {
        float s = b1[tid];
        #pragma unroll 4
        for (int d = 0; d < 192; d++) s += pool[d] * w1[d * 48 + tid];
        hid[tid] = eluf(s);
    }
    __syncthreads();
    if (tid < 2) {
        float s = b2[tid];
        #pragma unroll
        for (int d = 0; d < 48; d++) s += hid[d] * w2[d * 2 + tid];
        g_gates[b * 2 + tid] = 1.f / (1.f + __expf(-s));
    }
}

// ---------------- 8. final projection + output ----------------
__global__ void k_final(const float* __restrict__ proj_w, const float* __restrict__ proj_b,
                        float* __restrict__ out)
{
    __shared__ float gt[288];
    int b = blockIdx.x, tid = threadIdx.x;
    if (tid < 288) {
        int slot = 2 + tid / 96;
        int col = tid % 96;
        float s = 0.f;
        #pragma unroll
        for (int c = 0; c < 8; c++) s += g_pool[((slot * 8 + c) * BB + b) * HIDD + col];
        gt[tid] = s * (1.f / NN);
    }
    __syncthreads();
    if (tid < 128) {
        float s = proj_b[tid];
        #pragma unroll 4
        for (int d = 0; d < 288; d++) s += gt[d] * proj_w[d * 128 + tid];
        out[b * 128 + tid] = eluf(s);
    }
    if (tid == 128) {
        out[BB * 128 + b]      = g_gates[b * 2];
        out[BB * 128 + BB + b] = g_gates[b * 2 + 1];
    }
}

// ---------------- launch ----------------
extern "C" void kernel_launch(void* const* d_in, const int* in_sizes, int n_in,
                              void* d_out, int out_size)
{
    const float* x      = (const float*)d_in[0];
    const int*   adj    = (const int*)  d_in[1];
    const float* ln_g   = (const float*)d_in[2];
    const float* ln_b   = (const float*)d_in[3];
    const float* pre_w  = (const float*)d_in[4];
    const float* pre_b  = (const float*)d_in[5];
    const float* g1_w   = (const float*)d_in[6];
    const float* g1_as  = (const float*)d_in[7];
    const float* g1_ad  = (const float*)d_in[8];
    const float* g2_w   = (const float*)d_in[9];
    const float* g2_as  = (const float*)d_in[10];
    const float* g2_ad  = (const float*)d_in[11];
    const float* g3_w   = (const float*)d_in[12];
    const float* g3_as  = (const float*)d_in[13];
    const float* g3_ad  = (const float*)d_in[14];
    const float* g4_w   = (const float*)d_in[15];
    const float* g4_as  = (const float*)d_in[16];
    const float* g4_ad  = (const float*)d_in[17];
    const float* g5_w   = (const float*)d_in[18];
    const float* g5_as  = (const float*)d_in[19];
    const float* g5_ad  = (const float*)d_in[20];
    const float* gate_w1= (const float*)d_in[21];
    const float* gate_b1= (const float*)d_in[22];
    const float* gate_w2= (const float*)d_in[23];
    const float* gate_b2= (const float*)d_in[24];
    const float* proj_w = (const float*)d_in[25];
    const float* proj_b = (const float*)d_in[26];
    float* out = (float*)d_out;

    k_adjbits<<<4096, 256>>>(adj);
    k_ln_pre<<<BB * NN / 8, 256>>>(x, ln_g, ln_b, pre_w, pre_b);

    // gat1 (x0 -> x1): H=3, D=32
    k_gemm_h<<<BB * NN / 8, 256>>>(0, 0, 0, 0, 0, g1_w, g1_as, g1_ad, 3);
    k_prep2<<<BB * 3, 1024>>>();
    k_aggT<32><<<dim3(NN / 64, BB * 3), 256>>>(1, 3);

    // gat2 (x1 -> x2): H=1, D=96
    k_gemm_h<<<BB * NN / 8, 256>>>(1, 0, 0, 0, 0, g2_w, g2_as, g2_ad, 1);
    k_prep2<<<BB, 1024>>>();
    k_aggT<96><<<dim3(NN / 64, BB), 256>>>(2, 1);

    // gates from pooled means of x1, x2
    k_pool<<<dim3(BB, 8), 96>>>(1, 0);
    k_pool<<<dim3(BB, 8), 96>>>(2, 1);
    k_gates<<<BB, 256>>>(gate_w1, gate_b1, gate_w2, gate_b2);

    // gat4 on td_in = (1-wt)x1 + wt x2 -> x4
    k_gemm_h<<<BB * NN / 8, 256>>>(1, 2, 0, 1, 0, g4_w, g4_as, g4_ad, 1);
    k_prep2<<<BB, 1024>>>();
    k_aggT<96><<<dim3(NN / 64, BB), 256>>>(4, 1);

    // gat5 on ra_in = (1-wr)x1 + wr x2 -> x5
    k_gemm_h<<<BB * NN / 8, 256>>>(1, 2, 0, 1, 1, g5_w, g5_as, g5_ad, 1);
    k_prep2<<<BB, 1024>>>();
    k_aggT<96><<<dim3(NN / 64, BB), 256>>>(5, 1);

    // gat3 on stage_in = x2 + 0.5*(wt x4 + wr x5) -> x3
    k_gemm_h<<<BB * NN / 8, 256>>>(2, 4, 5, 2, 0, g3_w, g3_as, g3_ad, 1);
    k_prep2<<<BB, 1024>>>();
    k_aggT<96><<<dim3(NN / 64, BB), 256>>>(3, 1);

    // pooled means of x3, x4, x5 + final projection + output
    k_pool<<<dim3(BB, 8), 96>>>(3, 2);
    k_pool<<<dim3(BB, 8), 96>>>(4, 3);
    k_pool<<<dim3(BB, 8), 96>>>(5, 4);
    k_final<<<BB, 288>>>(proj_w, proj_b, out);
}

// round 5
// speedup vs baseline: 4.4848x; 1.5761x over previous
#include <cuda_runtime.h>
#include <math.h>
#include <stdint.h>

// ---------------- problem constants ----------------
#define BB   8
#define NN   1024
#define IND  64
#define HIDD 96
#define NEG  0.2f

// ---------------- scratch (device globals) ----------------
__device__ float    g_x[6][BB * NN * HIDD];        // x0..x5
__device__ float    g_hT[BB * HIDD * NN];          // h transposed: [b][col][n]
__device__ float    g_es[BB * 3 * NN];
__device__ float    g_ed[BB * 3 * NN];
__device__ unsigned g_adjb[NN * NN / 32];
__device__ float    g_gates[BB * 2];
__device__ float    g_poolc[5 * 16 * BB * HIDD];   // [slot][chunk16][b][col]

// ---------------- helpers ----------------
__device__ __forceinline__ float warpSum(float v) {
    #pragma unroll
    for (int o = 16; o; o >>= 1) v += __shfl_xor_sync(0xffffffffu, v, o);
    return v;
}
__device__ __forceinline__ float warpMax(float v) {
    #pragma unroll
    for (int o = 16; o; o >>= 1) v = fmaxf(v, __shfl_xor_sync(0xffffffffu, v, o));
    return v;
}
__device__ __forceinline__ float eluf(float x) { return x > 0.f ? x : expm1f(x); }
__device__ __forceinline__ float* bufsel(int id) { return g_x[id]; }

__device__ __forceinline__ uint32_t to_tf32(float f) {
    uint32_t u;
    asm("cvt.rna.tf32.f32 %0, %1;" : "=r"(u) : "f"(f));
    return u;
}
__device__ __forceinline__ void mma_tf32(float* c, uint32_t a0, uint32_t a1,
                                         uint32_t a2, uint32_t a3,
                                         uint32_t b0, uint32_t b1) {
    asm volatile(
        "mma.sync.aligned.m16n8k8.row.col.f32.tf32.tf32.f32 "
        "{%0,%1,%2,%3}, {%4,%5,%6,%7}, {%8,%9}, {%0,%1,%2,%3};"
        : "+f"(c[0]), "+f"(c[1]), "+f"(c[2]), "+f"(c[3])
        : "r"(a0), "r"(a1), "r"(a2), "r"(a3), "r"(b0), "r"(b1));
}

// ---------------- 1. adjacency -> bitmask ----------------
__global__ void k_adjbits(const int* __restrict__ adj) {
    int gw   = (blockIdx.x * blockDim.x + threadIdx.x) >> 5;
    int lane = threadIdx.x & 31;
    unsigned m = __ballot_sync(0xffffffffu, adj[gw * 32 + lane] > 0);
    if (lane == 0) g_adjb[gw] = m;
}

// ---------------- 2. LayerNorm + pre Linear + ELU -> x0 ----------------
__global__ __launch_bounds__(256) void k_ln_pre(
    const float* __restrict__ x, const float* __restrict__ ln_g,
    const float* __restrict__ ln_b, const float* __restrict__ W,
    const float* __restrict__ bias)
{
    __shared__ float Ws[IND * HIDD];
    __shared__ float xs[8][IND];
    int tid = threadIdx.x, warp = tid >> 5, lane = tid & 31;
    for (int i = tid; i < IND * HIDD; i += 256) Ws[i] = W[i];

    int row = blockIdx.x * 8 + warp;
    const float* xr = x + row * IND;
    float v0 = xr[lane], v1 = xr[lane + 32];
    float mu = warpSum(v0 + v1) * (1.f / IND);
    float d0 = v0 - mu, d1 = v1 - mu;
    float var = warpSum(d0 * d0 + d1 * d1) * (1.f / IND);
    float rs = rsqrtf(var + 1e-5f);
    xs[warp][lane]      = d0 * rs * ln_g[lane]      + ln_b[lane];
    xs[warp][lane + 32] = d1 * rs * ln_g[lane + 32] + ln_b[lane + 32];
    __syncthreads();

    float a0 = bias[lane], a1 = bias[lane + 32], a2 = bias[lane + 64];
    #pragma unroll
    for (int d = 0; d < IND; d++) {
        float xv = xs[warp][d];
        a0 += xv * Ws[d * HIDD + lane];
        a1 += xv * Ws[d * HIDD + lane + 32];
        a2 += xv * Ws[d * HIDD + lane + 64];
    }
    float* o = g_x[0] + row * HIDD;
    o[lane] = eluf(a0); o[lane + 32] = eluf(a1); o[lane + 64] = eluf(a2);
}

// ---------------- 3. h = mix(x) @ W via tf32 MMA, es/ed, hT store ----------------
// block = 64 rows, 256 thr = 8 warps in 4x2 (mi = wid>>1, nj = wid&1).
// dynamic smem: Ws_u[96][104] | union{ in_s[64][100] tf32, out_s[64][97] f32 } | as/ad
#define GH_WS   0
#define GH_TILE 39936
#define GH_AV   (39936 + 25600)
#define GH_SMEM (GH_AV + 768)

__global__ __launch_bounds__(256) void k_gemmh(
    int ia, int ib, int ic, int mode, int gidx,
    const float* __restrict__ W, const float* __restrict__ a_src,
    const float* __restrict__ a_dst, int H)
{
    extern __shared__ char dsm[];
    uint32_t* Ws_u  = (uint32_t*)(dsm + GH_WS);
    uint32_t* in_s  = (uint32_t*)(dsm + GH_TILE);
    float*    out_s = (float*)(dsm + GH_TILE);
    float*    as_s  = (float*)(dsm + GH_AV);
    float*    ad_s  = as_s + 96;

    int tid = threadIdx.x, wid = tid >> 5, lane = tid & 31;
    int g = lane >> 2, tg = lane & 3;
    int row0 = blockIdx.x * 64;
    int b = row0 >> 10, nb = row0 & (NN - 1);

    float c_a = 1.f, c_b = 0.f, c_c = 0.f;
    if (mode == 1) { float gg = g_gates[b * 2 + gidx]; c_a = 1.f - gg; c_b = gg; }
    else if (mode == 2) { c_b = 0.5f * g_gates[b * 2]; c_c = 0.5f * g_gates[b * 2 + 1]; }

    for (int i = tid; i < 96 * 96; i += 256) {
        int r = i / 96, c = i - r * 96;
        Ws_u[r * 104 + c] = to_tf32(W[i]);
    }
    if (tid < 96) { as_s[tid] = a_src[tid]; ad_s[tid] = a_dst[tid]; }

    const float* A  = bufsel(ia) + row0 * HIDD;
    const float* Bp = bufsel(ib) + row0 * HIDD;
    const float* Cp = bufsel(ic) + row0 * HIDD;
    for (int idx = tid; idx < 64 * 96; idx += 256) {
        int r = idx / 96, c = idx - r * 96;
        float v = c_a * A[idx];
        if (mode >= 1) v += c_b * Bp[idx];
        if (mode == 2) v += c_c * Cp[idx];
        in_s[r * 100 + c] = to_tf32(v);
    }
    __syncthreads();

    int mrow = (wid >> 1) * 16;
    int n0 = (wid & 1) * 48;
    float acc[6][4];
    #pragma unroll
    for (int nt = 0; nt < 6; nt++)
        #pragma unroll
        for (int q = 0; q < 4; q++) acc[nt][q] = 0.f;

    #pragma unroll
    for (int kt = 0; kt < 12; kt++) {
        int kl = kt * 8 + tg;
        uint32_t a0 = in_s[(mrow + g) * 100 + kl];
        uint32_t a1 = in_s[(mrow + g + 8) * 100 + kl];
        uint32_t a2 = in_s[(mrow + g) * 100 + kl + 4];
        uint32_t a3 = in_s[(mrow + g + 8) * 100 + kl + 4];
        #pragma unroll
        for (int nt = 0; nt < 6; nt++) {
            uint32_t b0 = Ws_u[kl * 104 + n0 + nt * 8 + g];
            uint32_t b1 = Ws_u[(kl + 4) * 104 + n0 + nt * 8 + g];
            mma_tf32(acc[nt], a0, a1, a2, a3, b0, b1);
        }
    }
    __syncthreads();   // in_s dead; reuse as out_s

    #pragma unroll
    for (int nt = 0; nt < 6; nt++) {
        int col = n0 + nt * 8 + tg * 2;
        out_s[(mrow + g) * 97 + col]       = acc[nt][0];
        out_s[(mrow + g) * 97 + col + 1]   = acc[nt][1];
        out_s[(mrow + g + 8) * 97 + col]   = acc[nt][2];
        out_s[(mrow + g + 8) * 97 + col + 1] = acc[nt][3];
    }
    __syncthreads();

    // transposed hT store (coalesced in n)
    float* hT = g_hT + (size_t)b * HIDD * NN;
    int n_loc = tid & 63, dg = tid >> 6;
    #pragma unroll
    for (int t = 0; t < 24; t++) {
        int d = dg * 24 + t;
        hT[(size_t)d * NN + nb + n_loc] = out_s[n_loc * 97 + d];
    }

    // es/ed: warp wid handles rows wid*8 .. +7
    #pragma unroll
    for (int rr = 0; rr < 8; rr++) {
        int r = wid * 8 + rr;
        float v0 = out_s[r * 97 + lane];
        float v1 = out_s[r * 97 + 32 + lane];
        float v2 = out_s[r * 97 + 64 + lane];
        float s0v = v0 * as_s[lane], s1v = v1 * as_s[lane + 32], s2v = v2 * as_s[lane + 64];
        float d0v = v0 * ad_s[lane], d1v = v1 * ad_s[lane + 32], d2v = v2 * ad_s[lane + 64];
        int n = nb + r;
        if (H == 1) {
            float ps = warpSum(s0v + s1v + s2v);
            float pd = warpSum(d0v + d1v + d2v);
            if (lane == 0) { g_es[b * NN + n] = ps; g_ed[b * NN + n] = pd; }
        } else {
            float s0 = warpSum(s0v), s1 = warpSum(s1v), s2 = warpSum(s2v);
            float e0 = warpSum(d0v), e1 = warpSum(d1v), e2 = warpSum(d2v);
            if (lane == 0) {
                g_es[(b * 3 + 0) * NN + n] = s0; g_ed[(b * 3 + 0) * NN + n] = e0;
                g_es[(b * 3 + 1) * NN + n] = s1; g_ed[(b * 3 + 1) * NN + n] = e1;
                g_es[(b * 3 + 2) * NN + n] = s2; g_ed[(b * 3 + 2) * NN + n] = e2;
            }
        }
    }
}

// ---------------- 4. attention aggregation (mma.sync tf32) + inlined factors + pooling ----------------
// out^T[D x 64] = H^T (A, smem) @ W^T (B, regs). grid (16, B*H).
template <int D>
__global__ __launch_bounds__(256) void k_aggT(int outid, int H, int slot) {
    constexpr int MT_W = D / 32;
    constexpr int NT_W = 2;

    __shared__ uint32_t hs[D * 36];
    __shared__ float es_s[64], A1s[64], A2s[64], invs[64], rsums[64];
    __shared__ float eds[32], e1s[32], e2s[32];
    __shared__ unsigned ms[64];
    __shared__ float red[8];
    __shared__ float pools_s[D * 4];

    int tid = threadIdx.x, wid = tid >> 5, lane = tid & 31;
    int g = lane >> 2, tg = lane & 3;
    int mi = wid >> 2, ni = wid & 3;
    int bh = blockIdx.y, b = bh / H, head = bh - b * H, hoff = head * D;
    int i0 = blockIdx.x * 64;

    const float* hTb = g_hT + ((size_t)b * HIDD + hoff) * NN;

    // global ed max (per bh), then per-i factors
    {
        const float4* ed4 = (const float4*)(g_ed + bh * NN);
        float4 vv = ed4[tid];
        float mx = fmaxf(fmaxf(vv.x, vv.y), fmaxf(vv.z, vv.w));
        mx = warpMax(mx);
        if (lane == 0) red[wid] = mx;
    }
    __syncthreads();
    float maxed = fmaxf(fmaxf(fmaxf(red[0], red[1]), fmaxf(red[2], red[3])),
                        fmaxf(fmaxf(red[4], red[5]), fmaxf(red[6], red[7])));
    if (tid < 64) {
        float es = g_es[bh * NN + i0 + tid];
        es_s[tid] = es;
        float t = es + maxed;
        float m = t > 0.f ? t : NEG * t;
        A1s[tid] = __expf(t - m);
        A2s[tid] = __expf(NEG * t - m);
    }
    __syncthreads();

    float esb[NT_W], A1b[NT_W], A2b[NT_W], rs[NT_W];
    int ib_loc[NT_W];
    #pragma unroll
    for (int ntl = 0; ntl < NT_W; ntl++) {
        ib_loc[ntl] = (ni * NT_W + ntl) * 8 + g;
        esb[ntl] = es_s[ib_loc[ntl]];
        A1b[ntl] = A1s[ib_loc[ntl]];
        A2b[ntl] = A2s[ib_loc[ntl]];
        rs[ntl] = 0.f;
    }

    float acc[MT_W][NT_W][4];
    #pragma unroll
    for (int m = 0; m < MT_W; m++)
        #pragma unroll
        for (int n = 0; n < NT_W; n++)
            #pragma unroll
            for (int q = 0; q < 4; q++) acc[m][n][q] = 0.f;

    for (int c = 0; c < NN / 32; c++) {
        int j0 = c * 32;
        __syncthreads();
        #pragma unroll
        for (int it = 0; it < D * 32 / 256; it++) {
            int idx = tid + it * 256;
            int d = idx >> 5, jj = idx & 31;
            hs[d * 36 + jj] = to_tf32(hTb[(size_t)d * NN + j0 + jj]);
        }
        if (tid < 32) {
            float e = g_ed[bh * NN + j0 + tid];
            eds[tid] = e;
            float dd = e - maxed;
            e1s[tid] = __expf(dd);
            e2s[tid] = __expf(NEG * dd);
        } else if (tid >= 96 && tid < 160) {
            ms[tid - 96] = g_adjb[(i0 + tid - 96) * 32 + c];
        }
        __syncthreads();

        unsigned msb[NT_W];
        #pragma unroll
        for (int ntl = 0; ntl < NT_W; ntl++) msb[ntl] = ms[ib_loc[ntl]];

        #pragma unroll
        for (int kt = 0; kt < 4; kt++) {
            int jl = kt * 8 + tg, jh = jl + 4;
            float edl = eds[jl], e1l = e1s[jl], e2l = e2s[jl];
            float edh = eds[jh], e1h = e1s[jh], e2h = e2s[jh];
            uint32_t bf0[NT_W], bf1[NT_W];
            #pragma unroll
            for (int ntl = 0; ntl < NT_W; ntl++) {
                float t0 = esb[ntl] + edl;
                float w0 = (t0 > 0.f) ? A1b[ntl] * e1l : A2b[ntl] * e2l;
                w0 = ((msb[ntl] >> jl) & 1u) ? w0 : 0.f;
                float t1 = esb[ntl] + edh;
                float w1 = (t1 > 0.f) ? A1b[ntl] * e1h : A2b[ntl] * e2h;
                w1 = ((msb[ntl] >> jh) & 1u) ? w1 : 0.f;
                if (mi == 0) rs[ntl] += w0 + w1;
                bf0[ntl] = to_tf32(w0);
                bf1[ntl] = to_tf32(w1);
            }
            #pragma unroll
            for (int mt = 0; mt < MT_W; mt++) {
                int dr = (mi * (MT_W * 16)) + mt * 16 + g;
                uint32_t a0 = hs[dr * 36 + jl];
                uint32_t a1 = hs[(dr + 8) * 36 + jl];
                uint32_t a2 = hs[dr * 36 + jh];
                uint32_t a3 = hs[(dr + 8) * 36 + jh];
                #pragma unroll
                for (int ntl = 0; ntl < NT_W; ntl++)
                    mma_tf32(acc[mt][ntl], a0, a1, a2, a3, bf0[ntl], bf1[ntl]);
            }
        }
    }

    if (mi == 0) {
        #pragma unroll
        for (int ntl = 0; ntl < NT_W; ntl++) {
            float r = rs[ntl];
            r += __shfl_xor_sync(0xffffffffu, r, 1);
            r += __shfl_xor_sync(0xffffffffu, r, 2);
            if (tg == 0) rsums[ib_loc[ntl]] = r;
        }
    }
    __syncthreads();
    if (tid < 64) {
        float rv = rsums[tid];
        invs[tid] = (rv > 0.f) ? (1.f / rv) : 0.f;
    }
    __syncthreads();

    float* outp = bufsel(outid);
    float pool0[MT_W], pool8[MT_W];
    #pragma unroll
    for (int mt = 0; mt < MT_W; mt++) { pool0[mt] = 0.f; pool8[mt] = 0.f; }

    #pragma unroll
    for (int mt = 0; mt < MT_W; mt++) {
        int d = mi * (MT_W * 16) + mt * 16 + g;
        #pragma unroll
        for (int ntl = 0; ntl < NT_W; ntl++) {
            int iL = (ni * NT_W + ntl) * 8 + tg * 2;
            float inv0 = invs[iL], inv1 = invs[iL + 1];
            size_t r0 = (size_t)(b * NN + i0 + iL) * HIDD + hoff;
            size_t r1 = r0 + HIDD;
            float o0 = eluf(acc[mt][ntl][0] * inv0);
            float o1 = eluf(acc[mt][ntl][1] * inv1);
            float o2 = eluf(acc[mt][ntl][2] * inv0);
            float o3 = eluf(acc[mt][ntl][3] * inv1);
            outp[r0 + d]     = o0;
            outp[r1 + d]     = o1;
            outp[r0 + d + 8] = o2;
            outp[r1 + d + 8] = o3;
            pool0[mt] += o0 + o1;
            pool8[mt] += o2 + o3;
        }
    }
    // pooling partials: reduce over tg (i-direction), write [d][ni]
    #pragma unroll
    for (int mt = 0; mt < MT_W; mt++) {
        int d0 = mi * (MT_W * 16) + mt * 16 + g;
        float v0 = pool0[mt];
        v0 += __shfl_xor_sync(0xffffffffu, v0, 1);
        v0 += __shfl_xor_sync(0xffffffffu, v0, 2);
        float v8 = pool8[mt];
        v8 += __shfl_xor_sync(0xffffffffu, v8, 1);
        v8 += __shfl_xor_sync(0xffffffffu, v8, 2);
        if (tg == 0) {
            pools_s[d0 * 4 + ni] = v0;
            pools_s[(d0 + 8) * 4 + ni] = v8;
        }
    }
    __syncthreads();
    if (tid < D) {
        float s = pools_s[tid * 4] + pools_s[tid * 4 + 1] +
                  pools_s[tid * 4 + 2] + pools_s[tid * 4 + 3];
        g_poolc[((slot * 16 + blockIdx.x) * BB + b) * HIDD + hoff + tid] = s;
    }
}

// ---------------- 5. gate MLP ----------------
__global__ void k_gates(const float* __restrict__ w1, const float* __restrict__ b1,
                        const float* __restrict__ w2, const float* __restrict__ b2)
{
    __shared__ float pool[2 * HIDD];
    __shared__ float hid[48];
    int b = blockIdx.x, tid = threadIdx.x;
    if (tid < 192) {
        int slot = tid < 96 ? 0 : 1;
        int col = tid < 96 ? tid : tid - 96;
        float s = 0.f;
        #pragma unroll
        for (int c = 0; c < 16; c++) s += g_poolc[((slot * 16 + c) * BB + b) * HIDD + col];
        pool[tid] = s * (1.f / NN);
    }
    __syncthreads();
    if (tid < 48) {
        float s = b1[tid];
        #pragma unroll 4
        for (int d = 0; d < 192; d++) s += pool[d] * w1[d * 48 + tid];
        hid[tid] = eluf(s);
    }
    __syncthreads();
    if (tid < 2) {
        float s = b2[tid];
        #pragma unroll
        for (int d = 0; d < 48; d++) s += hid[d] * w2[d * 2 + tid];
        g_gates[b * 2 + tid] = 1.f / (1.f + __expf(-s));
    }
}

// ---------------- 6. final projection + output ----------------
__global__ void k_final(const float* __restrict__ proj_w, const float* __restrict__ proj_b,
                        float* __restrict__ out)
{
    __shared__ float gt[288];
    int b = blockIdx.x, tid = threadIdx.x;
    if (tid < 288) {
        int slot = 2 + tid / 96;
        int col = tid % 96;
        float s = 0.f;
        #pragma unroll
        for (int c = 0; c < 16; c++) s += g_poolc[((slot * 16 + c) * BB + b) * HIDD + col];
        gt[tid] = s * (1.f / NN);
    }
    __syncthreads();
    if (tid < 128) {
        float s = proj_b[tid];
        #pragma unroll 4
        for (int d = 0; d < 288; d++) s += gt[d] * proj_w[d * 128 + tid];
        out[b * 128 + tid] = eluf(s);
    }
    if (tid == 128) {
        out[BB * 128 + b]      = g_gates[b * 2];
        out[BB * 128 + BB + b] = g_gates[b * 2 + 1];
    }
}

// ---------------- launch ----------------
extern "C" void kernel_launch(void* const* d_in, const int* in_sizes, int n_in,
                              void* d_out, int out_size)
{
    const float* x      = (const float*)d_in[0];
    const int*   adj    = (const int*)  d_in[1];
    const float* ln_g   = (const float*)d_in[2];
    const float* ln_b   = (const float*)d_in[3];
    const float* pre_w  = (const float*)d_in[4];
    const float* pre_b  = (const float*)d_in[5];
    const float* g1_w   = (const float*)d_in[6];
    const float* g1_as  = (const float*)d_in[7];
    const float* g1_ad  = (const float*)d_in[8];
    const float* g2_w   = (const float*)d_in[9];
    const float* g2_as  = (const float*)d_in[10];
    const float* g2_ad  = (const float*)d_in[11];
    const float* g3_w   = (const float*)d_in[12];
    const float* g3_as  = (const float*)d_in[13];
    const float* g3_ad  = (const float*)d_in[14];
    const float* g4_w   = (const float*)d_in[15];
    const float* g4_as  = (const float*)d_in[16];
    const float* g4_ad  = (const float*)d_in[17];
    const float* g5_w   = (const float*)d_in[18];
    const float* g5_as  = (const float*)d_in[19];
    const float* g5_ad  = (const float*)d_in[20];
    const float* gate_w1= (const float*)d_in[21];
    const float* gate_b1= (const float*)d_in[22];
    const float* gate_w2= (const float*)d_in[23];
    const float* gate_b2= (const float*)d_in[24];
    const float* proj_w = (const float*)d_in[25];
    const float* proj_b = (const float*)d_in[26];
    float* out = (float*)d_out;

    cudaFuncSetAttribute(k_gemmh, cudaFuncAttributeMaxDynamicSharedMemorySize, GH_SMEM);

    k_adjbits<<<4096, 256>>>(adj);
    k_ln_pre<<<BB * NN / 8, 256>>>(x, ln_g, ln_b, pre_w, pre_b);

    // gat1 (x0 -> x1): H=3, D=32; x1 pooled to slot 0
    k_gemmh<<<BB * NN / 64, 256, GH_SMEM>>>(0, 0, 0, 0, 0, g1_w, g1_as, g1_ad, 3);
    k_aggT<32><<<dim3(16, BB * 3), 256>>>(1, 3, 0);

    // gat2 (x1 -> x2): H=1, D=96; x2 pooled to slot 1
    k_gemmh<<<BB * NN / 64, 256, GH_SMEM>>>(1, 0, 0, 0, 0, g2_w, g2_as, g2_ad, 1);
    k_aggT<96><<<dim3(16, BB), 256>>>(2, 1, 1);

    k_gates<<<BB, 256>>>(gate_w1, gate_b1, gate_w2, gate_b2);

    // gat4 on td_in = (1-wt)x1 + wt x2 -> x4 (slot 3)
    k_gemmh<<<BB * NN / 64, 256, GH_SMEM>>>(1, 2, 0, 1, 0, g4_w, g4_as, g4_ad, 1);
    k_aggT<96><<<dim3(16, BB), 256>>>(4, 1, 3);

    // gat5 on ra_in = (1-wr)x1 + wr x2 -> x5 (slot 4)
    k_gemmh<<<BB * NN / 64, 256, GH_SMEM>>>(1, 2, 0, 1, 1, g5_w, g5_as, g5_ad, 1);
    k_aggT<96><<<dim3(16, BB), 256>>>(5, 1, 4);

    // gat3 on stage_in = x2 + 0.5*(wt x4 + wr x5) -> x3 (slot 2)
    k_gemmh<<<BB * NN / 64, 256, GH_SMEM>>>(2, 4, 5, 2, 0, g3_w, g3_as, g3_ad, 1);
    k_aggT<96><<<dim3(16, BB), 256>>>(3, 1, 2);

    k_final<<<BB, 288>>>(proj_w, proj_b, out);
}